// round 1
// baseline (speedup 1.0000x reference)
#include <cuda_runtime.h>
#include <math.h>

#define TT 4096
#define DD 4096
#define VV 32000

// ---------------- scratch (device globals; no allocations) ----------------
__device__ float g_pre0[TT];
__device__ float g_pre1[TT];
__device__ int   g_reset[TT];
__device__ float g_h0[TT];
__device__ float g_h1[TT];
__device__ float g_Bv[VV];
__device__ float g_C[121];

__device__ __constant__ float c_invfact[11] = {
    1.0f, 1.0f, 0.5f, 1.6666667e-1f, 4.1666668e-2f, 8.3333338e-3f,
    1.3888889e-3f, 1.9841270e-4f, 2.4801588e-5f, 2.7557319e-6f, 2.7557319e-7f
};

// accurate-enough tanh: exact +-1 in saturation (matches fp32 tanh rounding),
// ~1e-7 error elsewhere (EX2 + RCP)
__device__ __forceinline__ float tanh_acc(float a) {
    float ab = fabsf(a);
    if (ab > 9.1f) return copysignf(1.0f, a);
    float e = __expf(-2.0f * ab);
    float r = __fdividef(1.0f - e, 1.0f + e);
    return copysignf(r, a);
}

// ---------------- K1: pre[t] = x[t] . W_ih rows + b_ih + b_hh, reset flags ----
__global__ __launch_bounds__(256) void k_pre(const float* __restrict__ x,
                                             const float* __restrict__ Wih,
                                             const float* __restrict__ bih,
                                             const float* __restrict__ bhh,
                                             const float* __restrict__ Whh) {
    int t = blockIdx.x;
    int tid = threadIdx.x;
    const float4* xr = (const float4*)(x + (size_t)t * DD);
    const float4* w0 = (const float4*)(Wih);
    const float4* w1 = (const float4*)(Wih + DD);
    float a0 = 0.f, a1 = 0.f;
#pragma unroll 4
    for (int i = tid; i < DD / 4; i += 256) {
        float4 xv = xr[i];
        float4 wa = w0[i];
        float4 wb = w1[i];
        a0 = fmaf(xv.x, wa.x, a0); a0 = fmaf(xv.y, wa.y, a0);
        a0 = fmaf(xv.z, wa.z, a0); a0 = fmaf(xv.w, wa.w, a0);
        a1 = fmaf(xv.x, wb.x, a1); a1 = fmaf(xv.y, wb.y, a1);
        a1 = fmaf(xv.z, wb.z, a1); a1 = fmaf(xv.w, wb.w, a1);
    }
#pragma unroll
    for (int o = 16; o; o >>= 1) {
        a0 += __shfl_down_sync(0xffffffffu, a0, o);
        a1 += __shfl_down_sync(0xffffffffu, a1, o);
    }
    __shared__ float s0[8], s1[8];
    if ((tid & 31) == 0) { s0[tid >> 5] = a0; s1[tid >> 5] = a1; }
    __syncthreads();
    if (tid == 0) {
        float p0 = bih[0] + bhh[0];
        float p1 = bih[1] + bhh[1];
#pragma unroll
        for (int w = 0; w < 8; w++) { p0 += s0[w]; p1 += s1[w]; }
        g_pre0[t] = p0;
        g_pre1[t] = p1;
        float th0 = 9.2f + fabsf(Whh[0]) + fabsf(Whh[1]);
        float th1 = 9.2f + fabsf(Whh[2]) + fabsf(Whh[3]);
        g_reset[t] = (fabsf(p0) > th0) && (fabsf(p1) > th1) ? 1 : 0;
    }
}

// ---------------- K2: segmented parallel scan at saturation reset points -----
__global__ __launch_bounds__(256) void k_scan(const float* __restrict__ Whh) {
    int idx = blockIdx.x * blockDim.x + threadIdx.x; // 0..TT (idx 0 == virtual reset at t=-1, h=0)
    if (idx > TT) return;
    float W00 = Whh[0], W01 = Whh[1], W10 = Whh[2], W11 = Whh[3];
    float h0, h1;
    int t;
    if (idx == 0) {
        h0 = 0.f; h1 = 0.f; t = 0;
    } else {
        int r = idx - 1;
        if (!g_reset[r]) return;
        // at a reset point h is exactly sign(pre): |pre_i| - |Whh row|_1 > 9.1 => tanh == +-1.0f
        h0 = copysignf(1.0f, g_pre0[r]);
        h1 = copysignf(1.0f, g_pre1[r]);
        g_h0[r] = h0;
        g_h1[r] = h1;
        t = r + 1;
    }
    while (t < TT && !g_reset[t]) {
        float p0 = g_pre0[t], p1 = g_pre1[t];
        float a0 = fmaf(W01, h1, fmaf(W00, h0, p0));
        float a1 = fmaf(W11, h1, fmaf(W10, h0, p1));
        h0 = tanh_acc(a0);
        h1 = tanh_acc(a1);
        g_h0[t] = h0;
        g_h1[t] = h1;
        t++;
    }
}

// ---------------- K3: Bv = exp(b_fc) ----------------
__global__ __launch_bounds__(256) void k_expb(const float* __restrict__ bfc) {
    int v = blockIdx.x * 256 + threadIdx.x;
    if (v < VV) g_Bv[v] = __expf(bfc[v]);
}

// ---------------- K4: bivariate Taylor moments C_jk of sumexp ----------------
__global__ __launch_bounds__(256) void k_moments(const float* __restrict__ Wfc) {
    int j = blockIdx.x / 11;
    int k = blockIdx.x % 11;
    int tid = threadIdx.x;
    float acc = 0.f;
    for (int v = tid; v < VV; v += 256) {
        float w0 = Wfc[2 * v];
        float w1 = Wfc[2 * v + 1];
        float p = g_Bv[v];
        for (int a = 0; a < j; a++) p *= w0;
        for (int a = 0; a < k; a++) p *= w1;
        acc += p;
    }
#pragma unroll
    for (int o = 16; o; o >>= 1) acc += __shfl_down_sync(0xffffffffu, acc, o);
    __shared__ float s[8];
    if ((tid & 31) == 0) s[tid >> 5] = acc;
    __syncthreads();
    if (tid == 0) {
        float tot = 0.f;
#pragma unroll
        for (int w = 0; w < 8; w++) tot += s[w];
        g_C[blockIdx.x] = tot * c_invfact[j] * c_invfact[k];
    }
}

// ---------------- K5: logits write (HBM-write bound) ----------------
// grid (TT/16, 2): block.y splits the V range; 16 rows share one W_fc/b_fc pass
__global__ __launch_bounds__(256) void k_logits(const float* __restrict__ Wfc,
                                                const float* __restrict__ bfc,
                                                float* __restrict__ out) {
    __shared__ float sh0[16], sh1[16];
    int tb = blockIdx.x * 16;
    if (threadIdx.x < 16) {
        sh0[threadIdx.x] = g_h0[tb + threadIdx.x];
        sh1[threadIdx.x] = g_h1[tb + threadIdx.x];
    }
    __syncthreads();
    float h0r[16], h1r[16];
#pragma unroll
    for (int r = 0; r < 16; r++) { h0r[r] = sh0[r]; h1r[r] = sh1[r]; }

    const int vbeg = blockIdx.y * (VV / 2);
    const int vend = vbeg + (VV / 2);
    for (int v = vbeg + threadIdx.x * 4; v < vend; v += 1024) {
        float4 wa = *(const float4*)(Wfc + 2 * v);      // w0[v], w1[v], w0[v+1], w1[v+1]
        float4 wb = *(const float4*)(Wfc + 2 * v + 4);  // w0[v+2], w1[v+2], w0[v+3], w1[v+3]
        float4 b  = *(const float4*)(bfc + v);
#pragma unroll
        for (int r = 0; r < 16; r++) {
            float4 o;
            o.x = fmaf(h0r[r], wa.x, fmaf(h1r[r], wa.y, b.x));
            o.y = fmaf(h0r[r], wa.z, fmaf(h1r[r], wa.w, b.y));
            o.z = fmaf(h0r[r], wb.x, fmaf(h1r[r], wb.y, b.z));
            o.w = fmaf(h0r[r], wb.z, fmaf(h1r[r], wb.w, b.w));
            __stcs((float4*)(out + (size_t)(tb + r) * VV + v), o);
        }
    }
}

// ---------------- K6: per-row loss via Taylor sumexp + mean-reduce ----------
__global__ __launch_bounds__(1024) void k_loss(const float* __restrict__ Wfc,
                                               const float* __restrict__ bfc,
                                               const int* __restrict__ tgt_raw,
                                               float* __restrict__ out,
                                               long long loss_idx) {
    int tid = threadIdx.x;
    __shared__ float sC[121];
    if (tid < 121) sC[tid] = g_C[tid];

    // detect int64 vs int32 targets: int64 (LE) => all odd 32-bit words of the
    // first 4096 words are zero (values < 32000). OOB-safe for both layouts.
    int local = 0;
    for (int i = tid; i < TT / 2; i += 1024) local |= tgt_raw[2 * i + 1];
    int nz = __syncthreads_or(local);
    int is64 = (nz == 0);

    float acc = 0.f;
#pragma unroll
    for (int r = 0; r < 4; r++) {
        int t = r * 1024 + tid;
        float h0 = g_h0[t];
        float h1 = g_h1[t];
        // sumexp(h) = sum_{j,k<=10} C_jk h0^j h1^k  (double Horner)
        float S = 0.f;
#pragma unroll
        for (int j = 10; j >= 0; j--) {
            const float* row = &sC[j * 11];
            float inner = row[10];
#pragma unroll
            for (int k = 9; k >= 0; k--) inner = fmaf(inner, h1, row[k]);
            S = fmaf(S, h0, inner);
        }
        int g = is64 ? tgt_raw[2 * t] : tgt_raw[t];
        float lt = fmaf(h0, Wfc[2 * g], fmaf(h1, Wfc[2 * g + 1], bfc[g]));
        acc += logf(S) - lt;
    }

#pragma unroll
    for (int o = 16; o; o >>= 1) acc += __shfl_down_sync(0xffffffffu, acc, o);
    __shared__ float s[32];
    if ((tid & 31) == 0) s[tid >> 5] = acc;
    __syncthreads();
    if (tid == 0) {
        float tot = 0.f;
#pragma unroll
        for (int w = 0; w < 32; w++) tot += s[w];
        if (loss_idx >= 0) out[loss_idx] = tot * (1.0f / TT);
    }
}

// ---------------- launch ----------------
extern "C" void kernel_launch(void* const* d_in, const int* in_sizes, int n_in,
                              void* d_out, int out_size) {
    const float* x       = (const float*)d_in[0];
    const int*   targets = (const int*)d_in[1];   // int32 or int64, detected on device
    const float* Wih     = (const float*)d_in[2];
    const float* bih     = (const float*)d_in[3];
    const float* Whh     = (const float*)d_in[4];
    const float* bhh     = (const float*)d_in[5];
    const float* Wfc     = (const float*)d_in[6];
    const float* bfc     = (const float*)d_in[7];
    float* out = (float*)d_out;

    const long long logits_elems = (long long)TT * VV;

    k_pre<<<TT, 256>>>(x, Wih, bih, bhh, Whh);
    k_expb<<<(VV + 255) / 256, 256>>>(bfc);
    k_moments<<<121, 256>>>(Wfc);
    k_scan<<<(TT + 1 + 255) / 256, 256>>>(Whh);

    if ((long long)out_size >= logits_elems) {
        dim3 grid(TT / 16, 2, 1);
        k_logits<<<grid, 256>>>(Wfc, bfc, out);
    }

    long long loss_idx = -1;
    if ((long long)out_size > logits_elems) loss_idx = logits_elems;  // logits + loss
    else if (out_size == 1) loss_idx = 0;                             // loss only
    k_loss<<<1, 1024>>>(Wfc, bfc, targets, out, loss_idx);
}

// round 2
// speedup vs baseline: 1.3240x; 1.3240x over previous
#include <cuda_runtime.h>
#include <math.h>

#define TT 4096
#define DD 4096
#define VV 32000
#define PRE_BLOCKS 512   // 8 timesteps per block (warp per timestep)
#define MOM_BLOCKS 121

// ---------------- scratch (device globals; no allocations) ----------------
__device__ float g_pre0[TT];
__device__ float g_pre1[TT];
__device__ float g_h0[TT];
__device__ float g_h1[TT];
__device__ float g_C[121];

__device__ __constant__ float c_invfact[11] = {
    1.0f, 1.0f, 0.5f, 1.6666667e-1f, 4.1666668e-2f, 8.3333338e-3f,
    1.3888889e-3f, 1.9841270e-4f, 2.4801588e-5f, 2.7557319e-6f, 2.7557319e-7f
};

// accurate-enough tanh: exact +-1 in saturation (matches fp32 tanh rounding),
// ~1e-7 error elsewhere (EX2 + RCP)
__device__ __forceinline__ float tanh_acc(float a) {
    float ab = fabsf(a);
    if (ab > 9.1f) return copysignf(1.0f, a);
    float e = __expf(-2.0f * ab);
    float r = __fdividef(1.0f - e, 1.0f + e);
    return copysignf(r, a);
}

// ---------------- K1: fused pre-GEMV (warp-per-timestep) + Taylor moments ----
__global__ __launch_bounds__(256) void k1_pre_moments(const float* __restrict__ x,
                                                      const float* __restrict__ Wih,
                                                      const float* __restrict__ bih,
                                                      const float* __restrict__ bhh,
                                                      const float* __restrict__ Wfc,
                                                      const float* __restrict__ bfc) {
    int b = blockIdx.x;
    if (b < PRE_BLOCKS) {
        // ---- pre[t] = x[t] . W_ih rows + b_ih + b_hh, one warp per timestep ----
        int wid = threadIdx.x >> 5;
        int lid = threadIdx.x & 31;
        int t = b * 8 + wid;
        const float4* xr = (const float4*)(x + (size_t)t * DD);
        const float4* w0 = (const float4*)(Wih);
        const float4* w1 = (const float4*)(Wih + DD);
        float a0 = 0.f, a1 = 0.f;
#pragma unroll 8
        for (int i = lid; i < DD / 4; i += 32) {
            float4 xv = xr[i];
            float4 wa = w0[i];
            float4 wb = w1[i];
            a0 = fmaf(xv.x, wa.x, a0); a0 = fmaf(xv.y, wa.y, a0);
            a0 = fmaf(xv.z, wa.z, a0); a0 = fmaf(xv.w, wa.w, a0);
            a1 = fmaf(xv.x, wb.x, a1); a1 = fmaf(xv.y, wb.y, a1);
            a1 = fmaf(xv.z, wb.z, a1); a1 = fmaf(xv.w, wb.w, a1);
        }
#pragma unroll
        for (int o = 16; o; o >>= 1) {
            a0 += __shfl_down_sync(0xffffffffu, a0, o);
            a1 += __shfl_down_sync(0xffffffffu, a1, o);
        }
        if (lid == 0) {
            g_pre0[t] = a0 + bih[0] + bhh[0];
            g_pre1[t] = a1 + bih[1] + bhh[1];
        }
    } else {
        // ---- moments C_jk = (1/j!k!) sum_v exp(bfc_v) w0_v^j w1_v^k ----
        int m = b - PRE_BLOCKS;
        int j = m / 11;
        int k = m % 11;
        int tid = threadIdx.x;
        float acc = 0.f;
        for (int v = tid; v < VV; v += 256) {
            float2 w = *(const float2*)(Wfc + 2 * v);
            float p = __expf(bfc[v]);
            for (int a = 0; a < j; a++) p *= w.x;
            for (int a = 0; a < k; a++) p *= w.y;
            acc += p;
        }
#pragma unroll
        for (int o = 16; o; o >>= 1) acc += __shfl_down_sync(0xffffffffu, acc, o);
        __shared__ float s[8];
        if ((tid & 31) == 0) s[tid >> 5] = acc;
        __syncthreads();
        if (tid == 0) {
            float tot = 0.f;
#pragma unroll
            for (int w = 0; w < 8; w++) tot += s[w];
            g_C[m] = tot * c_invfact[j] * c_invfact[k];
        }
    }
}

// ---------------- K2: segmented scan, single block, pre staged in SMEM -------
__global__ __launch_bounds__(1024) void k2_scan(const float* __restrict__ Whh) {
    __shared__ float sp0[TT];
    __shared__ float sp1[TT];
    int tid = threadIdx.x;
    for (int i = tid; i < TT; i += 1024) {
        sp0[i] = g_pre0[i];
        sp1[i] = g_pre1[i];
    }
    __syncthreads();

    float W00 = Whh[0], W01 = Whh[1], W10 = Whh[2], W11 = Whh[3];
    float th0 = 9.2f + fabsf(W00) + fabsf(W01);
    float th1 = 9.2f + fabsf(W10) + fabsf(W11);

#pragma unroll
    for (int k = 0; k < 5; k++) {
        int idx = tid + k * 1024;           // starter index 0..TT
        if (k == 4 && tid != 0) break;      // only thread 0 handles idx==TT
        if (k == 4) idx = TT;

        float h0, h1;
        int t;
        if (idx == 0) {
            h0 = 0.f; h1 = 0.f; t = 0;
        } else {
            int r = idx - 1;
            float p0 = sp0[r], p1 = sp1[r];
            if (!(fabsf(p0) > th0 && fabsf(p1) > th1)) continue;  // not a reset point
            h0 = copysignf(1.0f, p0);   // saturated: tanh == +-1.0f exactly
            h1 = copysignf(1.0f, p1);
            g_h0[r] = h0;
            g_h1[r] = h1;
            t = r + 1;
        }
        while (t < TT) {
            float p0 = sp0[t], p1 = sp1[t];
            if (fabsf(p0) > th0 && fabsf(p1) > th1) break;  // next reset owns t
            float a0 = fmaf(W01, h1, fmaf(W00, h0, p0));
            float a1 = fmaf(W11, h1, fmaf(W10, h0, p1));
            h0 = tanh_acc(a0);
            h1 = tanh_acc(a1);
            g_h0[t] = h0;
            g_h1[t] = h1;
            t++;
        }
    }
}

// ---------------- K3: logits (HBM-write bound) + loss fused -------------------
// logits blocks: b in [0, 2048): t-tile = (b & 255)*16, v-chunk = (b >> 8)*4000
// loss block: b == gridDim.x-1 (256 threads, 16 rows each)
__global__ __launch_bounds__(256) void k3_logits_loss(const float* __restrict__ Wfc,
                                                      const float* __restrict__ bfc,
                                                      const int* __restrict__ tgt_raw,
                                                      float* __restrict__ out,
                                                      long long loss_idx,
                                                      int n_logit_blocks) {
    int b = blockIdx.x;
    int tid = threadIdx.x;

    if (b < n_logit_blocks) {
        // ------------- logits -------------
        __shared__ float sh0[16], sh1[16];
        int tb = (b & 255) * 16;
        if (tid < 16) {
            sh0[tid] = g_h0[tb + tid];
            sh1[tid] = g_h1[tb + tid];
        }
        __syncthreads();
        float h0r[16], h1r[16];
#pragma unroll
        for (int r = 0; r < 16; r++) { h0r[r] = sh0[r]; h1r[r] = sh1[r]; }

        const int vbeg = (b >> 8) * 4000;
        const int vend = vbeg + 4000;
        for (int v = vbeg + tid * 4; v < vend; v += 1024) {
            float4 wa = *(const float4*)(Wfc + 2 * v);      // w0,w1 of v, v+1
            float4 wb = *(const float4*)(Wfc + 2 * v + 4);  // w0,w1 of v+2, v+3
            float4 bb = *(const float4*)(bfc + v);
#pragma unroll
            for (int r = 0; r < 16; r++) {
                float4 o;
                o.x = fmaf(h0r[r], wa.x, fmaf(h1r[r], wa.y, bb.x));
                o.y = fmaf(h0r[r], wa.z, fmaf(h1r[r], wa.w, bb.y));
                o.z = fmaf(h0r[r], wb.x, fmaf(h1r[r], wb.y, bb.z));
                o.w = fmaf(h0r[r], wb.z, fmaf(h1r[r], wb.w, bb.w));
                __stcs((float4*)(out + (size_t)(tb + r) * VV + v), o);
            }
        }
    } else {
        // ------------- loss (runs concurrently with logits blocks) -------------
        __shared__ float sC[121];
        if (tid < 121) sC[tid] = g_C[tid];

        // detect int64 vs int32 targets: int64 (LE) => all odd 32-bit words of
        // the first 4096 words are zero (values < 32000). OOB-safe either way.
        int local = 0;
        for (int i = tid; i < TT / 2; i += 256) local |= tgt_raw[2 * i + 1];
        int nz = __syncthreads_or(local);
        int is64 = (nz == 0);

        float acc = 0.f;
#pragma unroll
        for (int r = 0; r < 16; r++) {
            int t = r * 256 + tid;
            float h0 = g_h0[t];
            float h1 = g_h1[t];
            // sumexp(h) = sum_{j,k<=10} C_jk h0^j h1^k (double Horner)
            float S = 0.f;
#pragma unroll
            for (int j = 10; j >= 0; j--) {
                const float* row = &sC[j * 11];
                float inner = row[10];
#pragma unroll
                for (int k = 9; k >= 0; k--) inner = fmaf(inner, h1, row[k]);
                S = fmaf(S, h0, inner);
            }
            int g = is64 ? tgt_raw[2 * t] : tgt_raw[t];
            float lt = fmaf(h0, Wfc[2 * g], fmaf(h1, Wfc[2 * g + 1], bfc[g]));
            acc += logf(S) - lt;
        }

#pragma unroll
        for (int o = 16; o; o >>= 1) acc += __shfl_down_sync(0xffffffffu, acc, o);
        __shared__ float s[8];
        if ((tid & 31) == 0) s[tid >> 5] = acc;
        __syncthreads();
        if (tid == 0) {
            float tot = 0.f;
#pragma unroll
            for (int w = 0; w < 8; w++) tot += s[w];
            if (loss_idx >= 0) out[loss_idx] = tot * (1.0f / TT);
        }
    }
}

// ---------------- launch ----------------
extern "C" void kernel_launch(void* const* d_in, const int* in_sizes, int n_in,
                              void* d_out, int out_size) {
    const float* x       = (const float*)d_in[0];
    const int*   targets = (const int*)d_in[1];   // int32 or int64, detected on device
    const float* Wih     = (const float*)d_in[2];
    const float* bih     = (const float*)d_in[3];
    const float* Whh     = (const float*)d_in[4];
    const float* bhh     = (const float*)d_in[5];
    const float* Wfc     = (const float*)d_in[6];
    const float* bfc     = (const float*)d_in[7];
    float* out = (float*)d_out;

    const long long logits_elems = (long long)TT * VV;

    k1_pre_moments<<<PRE_BLOCKS + MOM_BLOCKS, 256>>>(x, Wih, bih, bhh, Wfc, bfc);
    k2_scan<<<1, 1024>>>(Whh);

    int n_logit_blocks = ((long long)out_size >= logits_elems) ? 2048 : 0;
    long long loss_idx = -1;
    if ((long long)out_size > logits_elems) loss_idx = logits_elems;  // logits + loss
    else if (out_size == 1) loss_idx = 0;                             // loss only
    k3_logits_loss<<<n_logit_blocks + 1, 256>>>(Wfc, bfc, targets, out,
                                                loss_idx, n_logit_blocks);
}

// round 3
// speedup vs baseline: 1.6062x; 1.2132x over previous
#include <cuda_runtime.h>
#include <math.h>

#define TT 4096
#define DD 4096
#define VV 32000
#define PRE_BLOCKS 256   // 16 timesteps per block (2 per warp)
#define MOM_BLOCKS 11    // one block per j-power

// ---------------- scratch (device globals; no allocations) ----------------
__device__ float g_pre0[TT];
__device__ float g_pre1[TT];
__device__ float g_h0[TT];
__device__ float g_h1[TT];
__device__ float g_C[121];

__device__ __constant__ float c_invfact[11] = {
    1.0f, 1.0f, 0.5f, 1.6666667e-1f, 4.1666668e-2f, 8.3333338e-3f,
    1.3888889e-3f, 1.9841270e-4f, 2.4801588e-5f, 2.7557319e-6f, 2.7557319e-7f
};

// accurate-enough tanh: exact +-1 in saturation (matches fp32 tanh rounding),
// ~1e-7 error elsewhere (EX2 + RCP)
__device__ __forceinline__ float tanh_acc(float a) {
    float ab = fabsf(a);
    if (ab > 9.1f) return copysignf(1.0f, a);
    float e = __expf(-2.0f * ab);
    float r = __fdividef(1.0f - e, 1.0f + e);
    return copysignf(r, a);
}

// ---------------- K1: fused pre-GEMV (SMEM W, streamed x) + Taylor moments --
__global__ __launch_bounds__(256) void k1_pre_moments(const float* __restrict__ x,
                                                      const float* __restrict__ Wih,
                                                      const float* __restrict__ bih,
                                                      const float* __restrict__ bhh,
                                                      const float* __restrict__ Wfc,
                                                      const float* __restrict__ bfc) {
    __shared__ float4 sW0[DD / 4];
    __shared__ float4 sW1[DD / 4];
    int b = blockIdx.x;
    int tid = threadIdx.x;

    if (b < PRE_BLOCKS) {
        // stage W_ih (both rows, 32KB) into SMEM once per block
        const float4* w0g = (const float4*)(Wih);
        const float4* w1g = (const float4*)(Wih + DD);
#pragma unroll
        for (int i = 0; i < 4; i++) {
            int idx = tid + i * 256;
            sW0[idx] = w0g[idx];
            sW1[idx] = w1g[idx];
        }
        __syncthreads();

        int wid = tid >> 5;
        int lid = tid & 31;
        int t0 = b * 16 + wid * 2;               // this warp owns rows t0, t0+1
        const float4* xa = (const float4*)(x + (size_t)t0 * DD);
        const float4* xb = xa + DD / 4;

        float a00 = 0.f, a01 = 0.f, a10 = 0.f, a11 = 0.f;
#pragma unroll 8
        for (int i = lid; i < DD / 4; i += 32) {
            float4 va = __ldcs(&xa[i]);
            float4 vb = __ldcs(&xb[i]);
            float4 w0 = sW0[i];
            float4 w1 = sW1[i];
            a00 = fmaf(va.x, w0.x, a00); a00 = fmaf(va.y, w0.y, a00);
            a00 = fmaf(va.z, w0.z, a00); a00 = fmaf(va.w, w0.w, a00);
            a01 = fmaf(va.x, w1.x, a01); a01 = fmaf(va.y, w1.y, a01);
            a01 = fmaf(va.z, w1.z, a01); a01 = fmaf(va.w, w1.w, a01);
            a10 = fmaf(vb.x, w0.x, a10); a10 = fmaf(vb.y, w0.y, a10);
            a10 = fmaf(vb.z, w0.z, a10); a10 = fmaf(vb.w, w0.w, a10);
            a11 = fmaf(vb.x, w1.x, a11); a11 = fmaf(vb.y, w1.y, a11);
            a11 = fmaf(vb.z, w1.z, a11); a11 = fmaf(vb.w, w1.w, a11);
        }
#pragma unroll
        for (int o = 16; o; o >>= 1) {
            a00 += __shfl_down_sync(0xffffffffu, a00, o);
            a01 += __shfl_down_sync(0xffffffffu, a01, o);
            a10 += __shfl_down_sync(0xffffffffu, a10, o);
            a11 += __shfl_down_sync(0xffffffffu, a11, o);
        }
        if (lid == 0) {
            float c0 = bih[0] + bhh[0];
            float c1 = bih[1] + bhh[1];
            g_pre0[t0]     = a00 + c0;
            g_pre1[t0]     = a01 + c1;
            g_pre0[t0 + 1] = a10 + c0;
            g_pre1[t0 + 1] = a11 + c1;
        }
    } else {
        // ---- moments: block j computes C_jk for all k (11 accumulators) ----
        int j = b - PRE_BLOCKS;     // 0..10
        float acc[11];
#pragma unroll
        for (int k = 0; k < 11; k++) acc[k] = 0.f;

        for (int v = tid; v < VV; v += 256) {
            float2 w = *(const float2*)(Wfc + 2 * v);
            float p = __expf(bfc[v]);
#pragma unroll
            for (int a = 0; a < 10; a++) {
                if (a < j) p *= w.x;
            }
#pragma unroll
            for (int k = 0; k < 11; k++) {
                acc[k] += p;
                p *= w.y;
            }
        }
        __shared__ float sred[8][11];
#pragma unroll
        for (int k = 0; k < 11; k++) {
#pragma unroll
            for (int o = 16; o; o >>= 1)
                acc[k] += __shfl_down_sync(0xffffffffu, acc[k], o);
        }
        if ((tid & 31) == 0) {
#pragma unroll
            for (int k = 0; k < 11; k++) sred[tid >> 5][k] = acc[k];
        }
        __syncthreads();
        if (tid < 11) {
            float tot = 0.f;
#pragma unroll
            for (int w = 0; w < 8; w++) tot += sred[w][tid];
            g_C[j * 11 + tid] = tot * c_invfact[j] * c_invfact[tid];
        }
    }
}

// ---------------- K2: segmented scan, single block, pre staged in SMEM -------
__global__ __launch_bounds__(1024) void k2_scan(const float* __restrict__ Whh) {
    __shared__ float sp0[TT];
    __shared__ float sp1[TT];
    int tid = threadIdx.x;
    for (int i = tid; i < TT; i += 1024) {
        sp0[i] = g_pre0[i];
        sp1[i] = g_pre1[i];
    }
    __syncthreads();

    float W00 = Whh[0], W01 = Whh[1], W10 = Whh[2], W11 = Whh[3];
    float th0 = 9.2f + fabsf(W00) + fabsf(W01);
    float th1 = 9.2f + fabsf(W10) + fabsf(W11);

#pragma unroll
    for (int k = 0; k < 5; k++) {
        int idx = tid + k * 1024;           // starter index 0..TT
        if (k == 4 && tid != 0) break;      // only thread 0 handles idx==TT
        if (k == 4) idx = TT;

        float h0, h1;
        int t;
        if (idx == 0) {
            h0 = 0.f; h1 = 0.f; t = 0;
        } else {
            int r = idx - 1;
            float p0 = sp0[r], p1 = sp1[r];
            if (!(fabsf(p0) > th0 && fabsf(p1) > th1)) continue;  // not a reset point
            h0 = copysignf(1.0f, p0);   // saturated: tanh == +-1.0f exactly
            h1 = copysignf(1.0f, p1);
            g_h0[r] = h0;
            g_h1[r] = h1;
            t = r + 1;
        }
        while (t < TT) {
            float p0 = sp0[t], p1 = sp1[t];
            if (fabsf(p0) > th0 && fabsf(p1) > th1) break;  // next reset owns t
            float a0 = fmaf(W01, h1, fmaf(W00, h0, p0));
            float a1 = fmaf(W11, h1, fmaf(W10, h0, p1));
            h0 = tanh_acc(a0);
            h1 = tanh_acc(a1);
            g_h0[t] = h0;
            g_h1[t] = h1;
            t++;
        }
    }
}

// ---------------- K3: logits (HBM-write bound, 32-row tiles) + loss fused ----
// logits blocks: b in [0, 1024): t-tile = (b & 127)*32, v-chunk = (b >> 7)*4000
// loss block: b == n_logit_blocks
__global__ __launch_bounds__(256) void k3_logits_loss(const float* __restrict__ Wfc,
                                                      const float* __restrict__ bfc,
                                                      const int* __restrict__ tgt_raw,
                                                      float* __restrict__ out,
                                                      long long loss_idx,
                                                      int n_logit_blocks) {
    int b = blockIdx.x;
    int tid = threadIdx.x;

    if (b < n_logit_blocks) {
        // ------------- logits -------------
        __shared__ float sh0[32], sh1[32];
        int tb = (b & 127) * 32;
        if (tid < 32) {
            sh0[tid] = g_h0[tb + tid];
            sh1[tid] = g_h1[tb + tid];
        }
        __syncthreads();
        float h0r[32], h1r[32];
#pragma unroll
        for (int r = 0; r < 32; r++) { h0r[r] = sh0[r]; h1r[r] = sh1[r]; }

        const int vbeg = (b >> 7) * 4000;
        const int vend = vbeg + 4000;
        for (int v = vbeg + tid * 4; v < vend; v += 1024) {
            float4 wa = *(const float4*)(Wfc + 2 * v);      // w0,w1 of v, v+1
            float4 wb = *(const float4*)(Wfc + 2 * v + 4);  // w0,w1 of v+2, v+3
            float4 bb = *(const float4*)(bfc + v);
            float* op = out + (size_t)tb * VV + v;
#pragma unroll
            for (int r = 0; r < 32; r++) {
                float4 o;
                o.x = fmaf(h0r[r], wa.x, fmaf(h1r[r], wa.y, bb.x));
                o.y = fmaf(h0r[r], wa.z, fmaf(h1r[r], wa.w, bb.y));
                o.z = fmaf(h0r[r], wb.x, fmaf(h1r[r], wb.y, bb.z));
                o.w = fmaf(h0r[r], wb.z, fmaf(h1r[r], wb.w, bb.w));
                __stcs((float4*)(op + (size_t)r * VV), o);
            }
        }
    } else {
        // ------------- loss (runs concurrently with logits blocks) -------------
        __shared__ float sC[121];
        if (tid < 121) sC[tid] = g_C[tid];

        // detect int64 vs int32 targets: int64 (LE) => all odd 32-bit words of
        // the first 4096 words are zero (values < 32000). OOB-safe either way.
        int local = 0;
        for (int i = tid; i < TT / 2; i += 256) local |= tgt_raw[2 * i + 1];
        int nz = __syncthreads_or(local);
        int is64 = (nz == 0);

        float acc = 0.f;
#pragma unroll
        for (int r = 0; r < 16; r++) {
            int t = r * 256 + tid;
            float h0 = g_h0[t];
            float h1 = g_h1[t];
            // sumexp(h) = sum_{j,k<=10} C_jk h0^j h1^k (double Horner)
            float S = 0.f;
#pragma unroll
            for (int j = 10; j >= 0; j--) {
                const float* row = &sC[j * 11];
                float inner = row[10];
#pragma unroll
                for (int k = 9; k >= 0; k--) inner = fmaf(inner, h1, row[k]);
                S = fmaf(S, h0, inner);
            }
            int g = is64 ? tgt_raw[2 * t] : tgt_raw[t];
            float lt = fmaf(h0, Wfc[2 * g], fmaf(h1, Wfc[2 * g + 1], bfc[g]));
            acc += logf(S) - lt;
        }

#pragma unroll
        for (int o = 16; o; o >>= 1) acc += __shfl_down_sync(0xffffffffu, acc, o);
        __shared__ float s[8];
        if ((tid & 31) == 0) s[tid >> 5] = acc;
        __syncthreads();
        if (tid == 0) {
            float tot = 0.f;
#pragma unroll
            for (int w = 0; w < 8; w++) tot += s[w];
            if (loss_idx >= 0) out[loss_idx] = tot * (1.0f / TT);
        }
    }
}

// ---------------- launch ----------------
extern "C" void kernel_launch(void* const* d_in, const int* in_sizes, int n_in,
                              void* d_out, int out_size) {
    const float* x       = (const float*)d_in[0];
    const int*   targets = (const int*)d_in[1];   // int32 or int64, detected on device
    const float* Wih     = (const float*)d_in[2];
    const float* bih     = (const float*)d_in[3];
    const float* Whh     = (const float*)d_in[4];
    const float* bhh     = (const float*)d_in[5];
    const float* Wfc     = (const float*)d_in[6];
    const float* bfc     = (const float*)d_in[7];
    float* out = (float*)d_out;

    const long long logits_elems = (long long)TT * VV;

    k1_pre_moments<<<PRE_BLOCKS + MOM_BLOCKS, 256>>>(x, Wih, bih, bhh, Wfc, bfc);
    k2_scan<<<1, 1024>>>(Whh);

    int n_logit_blocks = ((long long)out_size >= logits_elems) ? 1024 : 0;
    long long loss_idx = -1;
    if ((long long)out_size > logits_elems) loss_idx = logits_elems;  // logits + loss
    else if (out_size == 1) loss_idx = 0;                             // loss only
    k3_logits_loss<<<n_logit_blocks + 1, 256>>>(Wfc, bfc, targets, out,
                                                loss_idx, n_logit_blocks);
}